// round 10
// baseline (speedup 1.0000x reference)
#include <cuda_runtime.h>
#include <cuda_fp16.h>

#define TPB 256
#define NBLOCKS 608            // persistent; residency-agnostic (work stealing)
#define MAX_LAYERS 64
#define CHUNK 160              // float4 per warp-chunk: 4 A-f4 + 1 B-f4 per lane
typedef unsigned long long ull;

__device__ unsigned g_chunk_ctr;

__global__ void reset_ctr_kernel() { g_chunk_ctr = 0u; }

// ---------- packed f32x2 primitives ----------
__device__ __forceinline__ ull f2fma(ull a, ull b, ull c) {
    ull d; asm("fma.rn.f32x2 %0, %1, %2, %3;" : "=l"(d) : "l"(a), "l"(b), "l"(c)); return d;
}
__device__ __forceinline__ ull f2mul(ull a, ull b) {
    ull d; asm("mul.rn.f32x2 %0, %1, %2;" : "=l"(d) : "l"(a), "l"(b)); return d;
}
__device__ __forceinline__ ull f2add(ull a, ull b) {
    ull d; asm("add.rn.f32x2 %0, %1, %2;" : "=l"(d) : "l"(a), "l"(b)); return d;
}
__device__ __forceinline__ ull pkf(float lo, float hi) {
    ull r; asm("mov.b64 %0, {%1, %2};" : "=l"(r) : "f"(lo), "f"(hi)); return r;
}
__device__ __forceinline__ ull pk2(float x) { return pkf(x, x); }
__device__ __forceinline__ void unpku(ull v, unsigned& lo, unsigned& hi) {
    asm("mov.b64 {%0, %1}, %2;" : "=r"(lo), "=r"(hi) : "l"(v));
}
__device__ __forceinline__ ull pku(unsigned lo, unsigned hi) {
    ull r; asm("mov.b64 %0, {%1, %2};" : "=l"(r) : "r"(lo), "r"(hi)); return r;
}
__device__ __forceinline__ void unpkf(ull v, float& lo, float& hi) {
    asm("mov.b64 {%0, %1}, %2;" : "=f"(lo), "=f"(hi) : "l"(v));
}
__device__ __forceinline__ __half2 u2h(unsigned u) {
    __half2 h; *reinterpret_cast<unsigned*>(&h) = u; return h;
}

// MUFU-free packed tanh: Eigen-style 13/6 rational (normalized leading 1s).
// 16 f32x2 (fma pipe) + 4 alu + ~8 boundary MOVs. abs err ~1e-6.
__device__ __forceinline__ ull tanh2_fma(ull y) {
    const float C = 7.90531110763549805f;
    float ylo, yhi;
    unpkf(y, ylo, yhi);
    ylo = fminf(fmaxf(ylo, -C), C);                  // FMNMX (alu)
    yhi = fminf(fmaxf(yhi, -C), C);
    ull x  = pkf(ylo, yhi);
    ull x2 = f2mul(x, x);
    ull p = f2fma(x2, pk2(-5.641877e-14f), pk2(4.087423e-11f));
    p = f2fma(x2, p, pk2(-1.758383e-08f));
    p = f2fma(x2, p, pk2(1.046751e-05f));
    p = f2fma(x2, p, pk2(3.036104e-03f));
    p = f2fma(x2, p, pk2(0.13022513f));
    p = f2fma(x2, p, pk2(1.0f));
    p = f2mul(p, x);                                 // numerator
    ull q = f2fma(x2, pk2(2.448660e-04f), pk2(2.422274e-02f));
    q = f2fma(x2, q, pk2(0.46355807f));
    q = f2fma(x2, q, pk2(1.0f));                     // denominator >= 1
    unsigned qlo, qhi;
    unpku(q, qlo, qhi);
    ull r  = pku(0x7EF311C3u - qlo, 0x7EF311C3u - qhi);  // ~1/q seed
    ull nq = q ^ 0x8000000080000000ull;              // -q
    r = f2mul(r, f2fma(nq, r, pk2(2.0f)));           // Newton 1
    r = f2mul(r, f2fma(nq, r, pk2(2.0f)));           // Newton 2
    return f2mul(p, r);                              // tanh(x)
}

__device__ __forceinline__ __half2 tanh_h2(__half2 x) {
    __half2 y;
    asm("tanh.approx.f16x2 %0, %1;"
        : "=r"(*reinterpret_cast<unsigned int*>(&y))
        : "r"(*reinterpret_cast<const unsigned int*>(&x)));
    return y;
}

__device__ __forceinline__ float2 fin_norm(float x0, float x1,
                                           float f00, float f01, float f10, float f11) {
    float o0 = fmaf(f00, x0, f01 * x1);
    float o1 = fmaf(f10, x0, f11 * x1);
    float s  = fmaf(o0, o0, o1 * o1);
    float inv = rsqrtf(s);
    inv = inv * fmaf(-0.5f * s * inv, inv, 1.5f);
    if (s < 1e-24f) inv = 1e12f;                     // eps=1e-12 clamp
    return make_float2(o0 * inv, o1 * inv);
}

// Homogeneous hybrid + stealing, with VECTORIZED weight fetches:
//   A weights: one uint4 (4x half2, LDS.128) + one uint2 (biases, LDS.64)
//   B weights: three ulonglong2 (LDS.128 each)
// -> exactly 5 LDS per thread-layer (was up to 12 scalar LDS).
// Every thread: 8 MUFU-path points (4 half2 pairs) + 2 fma-path points.
// z-form: z = 2x for l>=1 (0.5 folded into W); final normalize is scale-invariant.
__global__ __launch_bounds__(TPB, 3) void nignet_kernel(
    const float4* __restrict__ pts,
    const float*  __restrict__ Ws,    // (L,2,2)
    const float*  __restrict__ bs,    // (L,2)
    const float*  __restrict__ fW,    // (2,2)
    float4* __restrict__ out,
    int nf4, int nchunks, int layers)
{
    __shared__ __align__(16) uint4      sA [MAX_LAYERS];     // A: w00,w01,w10,w11 (half2 each)
    __shared__ __align__(8)  uint2      sAb[MAX_LAYERS];     // A: b0,b1 (half2 each)
    __shared__ __align__(16) ulonglong2 sB [MAX_LAYERS][3];  // B: {w00,w01},{w10,w11},{b0,b1}
    __shared__ float sf[4];

    const int tid = threadIdx.x;
    if (tid < layers) {
        const float scl = (tid == 0) ? 1.0f : 0.5f;
        float4 w = ((const float4*)Ws)[tid];
        float2 b = ((const float2*)bs)[tid];
        float w00 = w.x * scl, w01 = w.y * scl, w10 = w.z * scl, w11 = w.w * scl;
        __half2 h;
        uint4 ua;
        h = __float2half2_rn(w00); ua.x = *reinterpret_cast<unsigned*>(&h);
        h = __float2half2_rn(w01); ua.y = *reinterpret_cast<unsigned*>(&h);
        h = __float2half2_rn(w10); ua.z = *reinterpret_cast<unsigned*>(&h);
        h = __float2half2_rn(w11); ua.w = *reinterpret_cast<unsigned*>(&h);
        sA[tid] = ua;
        uint2 ub;
        h = __float2half2_rn(b.x); ub.x = *reinterpret_cast<unsigned*>(&h);
        h = __float2half2_rn(b.y); ub.y = *reinterpret_cast<unsigned*>(&h);
        sAb[tid] = ub;
        sB[tid][0] = make_ulonglong2(pk2(w00), pk2(w01));
        sB[tid][1] = make_ulonglong2(pk2(w10), pk2(w11));
        sB[tid][2] = make_ulonglong2(pk2(b.x), pk2(b.y));
    }
    if (tid < 4) sf[tid] = fW[tid];
    __syncthreads();

    const int lane = tid & 31;
    const float f00 = sf[0], f01 = sf[1], f10 = sf[2], f11 = sf[3];
    const float4 zero4 = make_float4(0.f, 0.f, 0.f, 0.f);

    for (;;) {
        unsigned c = 0;
        if (lane == 0) c = atomicAdd(&g_chunk_ctr, 1u);
        c = __shfl_sync(0xFFFFFFFFu, c, 0);
        if (c >= (unsigned)nchunks) break;
        const int base = (int)c * CHUNK;

        const int i0 = base + lane,       i1 = base + 32 + lane;
        const int i2 = base + 64 + lane,  i3 = base + 96 + lane;
        const int i4 = base + 128 + lane;
        const bool v0 = i0 < nf4, v1 = i1 < nf4, v2 = i2 < nf4,
                   v3 = i3 < nf4, v4 = i4 < nf4;
        float4 P0 = v0 ? pts[i0] : zero4;
        float4 P1 = v1 ? pts[i1] : zero4;
        float4 P2 = v2 ? pts[i2] : zero4;
        float4 P3 = v3 ? pts[i3] : zero4;
        float4 PB = v4 ? pts[i4] : zero4;

        __half2 Xa0 = __floats2half2_rn(P0.x, P0.z), Xa1 = __floats2half2_rn(P0.y, P0.w);
        __half2 Xb0 = __floats2half2_rn(P1.x, P1.z), Xb1 = __floats2half2_rn(P1.y, P1.w);
        __half2 Xc0 = __floats2half2_rn(P2.x, P2.z), Xc1 = __floats2half2_rn(P2.y, P2.w);
        __half2 Xd0 = __floats2half2_rn(P3.x, P3.z), Xd1 = __floats2half2_rn(P3.y, P3.w);
        ull     XB0 = pkf(PB.x, PB.z),               XB1 = pkf(PB.y, PB.w);

        #pragma unroll 1
        for (int l = 0; l < layers; ++l) {
            const uint4 ua = sA[l];                       // 1x LDS.128
            const uint2 ub = sAb[l];                      // 1x LDS.64
            const ulonglong2 q0 = sB[l][0];               // 3x LDS.128
            const ulonglong2 q1 = sB[l][1];
            const ulonglong2 q2 = sB[l][2];
            const __half2 w00 = u2h(ua.x), w01 = u2h(ua.y);
            const __half2 w10 = u2h(ua.z), w11 = u2h(ua.w);
            const __half2 hb0 = u2h(ub.x), hb1 = u2h(ub.y);

            // B pair first: long fma chain overlaps the A MUFU waits
            ull yB0 = f2fma(q0.x, XB0, f2fma(q0.y, XB1, q2.x));
            ull yB1 = f2fma(q1.x, XB0, f2fma(q1.y, XB1, q2.y));

            __half2 ya0 = __hfma2(w00, Xa0, __hfma2(w01, Xa1, hb0));
            __half2 ya1 = __hfma2(w10, Xa0, __hfma2(w11, Xa1, hb1));
            __half2 yb0 = __hfma2(w00, Xb0, __hfma2(w01, Xb1, hb0));
            __half2 yb1 = __hfma2(w10, Xb0, __hfma2(w11, Xb1, hb1));
            __half2 yc0 = __hfma2(w00, Xc0, __hfma2(w01, Xc1, hb0));
            __half2 yc1 = __hfma2(w10, Xc0, __hfma2(w11, Xc1, hb1));
            __half2 yd0 = __hfma2(w00, Xd0, __hfma2(w01, Xd1, hb0));
            __half2 yd1 = __hfma2(w10, Xd0, __hfma2(w11, Xd1, hb1));

            XB0 = f2add(tanh2_fma(yB0), yB0);
            XB1 = f2add(tanh2_fma(yB1), yB1);

            Xa0 = __hadd2(tanh_h2(ya0), ya0);
            Xa1 = __hadd2(tanh_h2(ya1), ya1);
            Xb0 = __hadd2(tanh_h2(yb0), yb0);
            Xb1 = __hadd2(tanh_h2(yb1), yb1);
            Xc0 = __hadd2(tanh_h2(yc0), yc0);
            Xc1 = __hadd2(tanh_h2(yc1), yc1);
            Xd0 = __hadd2(tanh_h2(yd0), yd0);
            Xd1 = __hadd2(tanh_h2(yd1), yd1);
        }

        {
            float2 a0 = __half22float2(Xa0), a1 = __half22float2(Xa1);
            float2 r0 = fin_norm(a0.x, a1.x, f00, f01, f10, f11);
            float2 r1 = fin_norm(a0.y, a1.y, f00, f01, f10, f11);
            if (v0) out[i0] = make_float4(r0.x, r0.y, r1.x, r1.y);
        }
        {
            float2 a0 = __half22float2(Xb0), a1 = __half22float2(Xb1);
            float2 r0 = fin_norm(a0.x, a1.x, f00, f01, f10, f11);
            float2 r1 = fin_norm(a0.y, a1.y, f00, f01, f10, f11);
            if (v1) out[i1] = make_float4(r0.x, r0.y, r1.x, r1.y);
        }
        {
            float2 a0 = __half22float2(Xc0), a1 = __half22float2(Xc1);
            float2 r0 = fin_norm(a0.x, a1.x, f00, f01, f10, f11);
            float2 r1 = fin_norm(a0.y, a1.y, f00, f01, f10, f11);
            if (v2) out[i2] = make_float4(r0.x, r0.y, r1.x, r1.y);
        }
        {
            float2 a0 = __half22float2(Xd0), a1 = __half22float2(Xd1);
            float2 r0 = fin_norm(a0.x, a1.x, f00, f01, f10, f11);
            float2 r1 = fin_norm(a0.y, a1.y, f00, f01, f10, f11);
            if (v3) out[i3] = make_float4(r0.x, r0.y, r1.x, r1.y);
        }
        {
            float b0x, b1x, b0y, b1y;
            unpkf(XB0, b0x, b1x);
            unpkf(XB1, b0y, b1y);
            float2 r0 = fin_norm(b0x, b0y, f00, f01, f10, f11);
            float2 r1 = fin_norm(b1x, b1y, f00, f01, f10, f11);
            if (v4) out[i4] = make_float4(r0.x, r0.y, r1.x, r1.y);
        }
    }
}

extern "C" void kernel_launch(void* const* d_in, const int* in_sizes, int n_in,
                              void* d_out, int out_size) {
    // metadata order: T(1), closed_manifold(N*2), Ws(L*4), bs(L*2), final_W(4)
    const float* pts = (const float*)d_in[1];
    const float* Ws  = (const float*)d_in[2];
    const float* bs  = (const float*)d_in[3];
    const float* fW  = (const float*)d_in[4];
    float* out = (float*)d_out;

    const int n       = in_sizes[1] / 2;
    const int layers  = in_sizes[2] / 4;
    const int nf4     = n / 2;
    const int nchunks = (nf4 + CHUNK - 1) / CHUNK;

    reset_ctr_kernel<<<1, 1>>>();
    nignet_kernel<<<NBLOCKS, TPB>>>(
        (const float4*)pts, Ws, bs, fW, (float4*)out, nf4, nchunks, layers);
}

// round 11
// speedup vs baseline: 1.0337x; 1.0337x over previous
#include <cuda_runtime.h>
#include <cuda_fp16.h>

#define TPB 512
#define NBLOCKS 304            // 152 SMs * 2 resident (persistent)
#define MAX_LAYERS 64
#define ACHUNK 128             // float4 per A-warp chunk (4/lane -> 8 pts/thread)
#define BCHUNK 96              // float4 per B-warp chunk (3/lane -> 6 pts/thread)
typedef unsigned long long ull;

__device__ unsigned g_ctrA, g_ctrB;

__global__ void reset_ctr_kernel() { g_ctrA = 0u; g_ctrB = 0u; }

// ---------- packed f32x2 primitives ----------
__device__ __forceinline__ ull f2fma(ull a, ull b, ull c) {
    ull d; asm("fma.rn.f32x2 %0, %1, %2, %3;" : "=l"(d) : "l"(a), "l"(b), "l"(c)); return d;
}
__device__ __forceinline__ ull f2mul(ull a, ull b) {
    ull d; asm("mul.rn.f32x2 %0, %1, %2;" : "=l"(d) : "l"(a), "l"(b)); return d;
}
__device__ __forceinline__ ull f2add(ull a, ull b) {
    ull d; asm("add.rn.f32x2 %0, %1, %2;" : "=l"(d) : "l"(a), "l"(b)); return d;
}
__device__ __forceinline__ ull pkf(float lo, float hi) {
    ull r; asm("mov.b64 %0, {%1, %2};" : "=l"(r) : "f"(lo), "f"(hi)); return r;
}
__device__ __forceinline__ ull pk2(float x) { return pkf(x, x); }
__device__ __forceinline__ void unpku(ull v, unsigned& lo, unsigned& hi) {
    asm("mov.b64 {%0, %1}, %2;" : "=r"(lo), "=r"(hi) : "l"(v));
}
__device__ __forceinline__ ull pku(unsigned lo, unsigned hi) {
    ull r; asm("mov.b64 %0, {%1, %2};" : "=l"(r) : "r"(lo), "r"(hi)); return r;
}
__device__ __forceinline__ void unpkf(ull v, float& lo, float& hi) {
    asm("mov.b64 {%0, %1}, %2;" : "=f"(lo), "=f"(hi) : "l"(v));
}
__device__ __forceinline__ __half2 u2h(unsigned u) {
    __half2 h; *reinterpret_cast<unsigned*>(&h) = u; return h;
}

// MUFU-free packed tanh: Eigen-style 13/6 rational. 16 f32x2 + 4 alu. err ~1e-6.
__device__ __forceinline__ ull tanh2_fma(ull y) {
    const float C = 7.90531110763549805f;
    float ylo, yhi;
    unpkf(y, ylo, yhi);
    ylo = fminf(fmaxf(ylo, -C), C);
    yhi = fminf(fmaxf(yhi, -C), C);
    ull x  = pkf(ylo, yhi);
    ull x2 = f2mul(x, x);
    ull p = f2fma(x2, pk2(-5.641877e-14f), pk2(4.087423e-11f));
    p = f2fma(x2, p, pk2(-1.758383e-08f));
    p = f2fma(x2, p, pk2(1.046751e-05f));
    p = f2fma(x2, p, pk2(3.036104e-03f));
    p = f2fma(x2, p, pk2(0.13022513f));
    p = f2fma(x2, p, pk2(1.0f));
    p = f2mul(p, x);                                 // numerator
    ull q = f2fma(x2, pk2(2.448660e-04f), pk2(2.422274e-02f));
    q = f2fma(x2, q, pk2(0.46355807f));
    q = f2fma(x2, q, pk2(1.0f));                     // denominator >= 1
    unsigned qlo, qhi;
    unpku(q, qlo, qhi);
    ull r  = pku(0x7EF311C3u - qlo, 0x7EF311C3u - qhi);
    ull nq = q ^ 0x8000000080000000ull;
    r = f2mul(r, f2fma(nq, r, pk2(2.0f)));
    r = f2mul(r, f2fma(nq, r, pk2(2.0f)));
    return f2mul(p, r);
}

__device__ __forceinline__ __half2 tanh_h2(__half2 x) {
    __half2 y;
    asm("tanh.approx.f16x2 %0, %1;"
        : "=r"(*reinterpret_cast<unsigned int*>(&y))
        : "r"(*reinterpret_cast<const unsigned int*>(&x)));
    return y;
}

__device__ __forceinline__ float2 fin_norm(float x0, float x1,
                                           float f00, float f01, float f10, float f11) {
    float o0 = fmaf(f00, x0, f01 * x1);
    float o1 = fmaf(f10, x0, f11 * x1);
    float s  = fmaf(o0, o0, o1 * o1);
    float inv = rsqrtf(s);
    inv = inv * fmaf(-0.5f * s * inv, inv, 1.5f);
    if (s < 1e-24f) inv = 1e12f;                     // eps=1e-12 clamp
    return make_float2(o0 * inv, o1 * inv);
}

// Warp-specialized persistent kernel with per-class work queues.
// Warps 0-11 = A (MUFU half2 tanh, pure-MUFU stream), warps 12-15 = B
// (fma-pipe rational tanh, pure-fma stream, 6 independent chains).
// SMSP = wid%4 -> every SMSP holds 3A+1B warps (x2 resident blocks).
// A steals 128-f4 chunks from [0,asplit); B steals 96-f4 chunks from
// [asplit,nf4). Queues drain independently: no churn, no convoying, 1-chunk tail.
// z-form: z = 2x for l>=1 (0.5 folded into W); final normalize is scale-invariant.
__global__ __launch_bounds__(TPB, 2) void nignet_kernel(
    const float4* __restrict__ pts,
    const float*  __restrict__ Ws,    // (L,2,2)
    const float*  __restrict__ bs,    // (L,2)
    const float*  __restrict__ fW,    // (2,2)
    float4* __restrict__ out,
    int nf4, int asplit, int nchA, int nchB, int layers)
{
    __shared__ __align__(16) uint4      sA [MAX_LAYERS];     // A: w00..w11 (half2 each)
    __shared__ __align__(8)  uint2      sAb[MAX_LAYERS];     // A: b0,b1 (half2 each)
    __shared__ __align__(16) ulonglong2 sB [MAX_LAYERS][3];  // B: {w00,w01},{w10,w11},{b0,b1}
    __shared__ float sf[4];

    const int tid = threadIdx.x;
    if (tid < layers) {
        const float scl = (tid == 0) ? 1.0f : 0.5f;
        float4 w = ((const float4*)Ws)[tid];
        float2 b = ((const float2*)bs)[tid];
        float w00 = w.x * scl, w01 = w.y * scl, w10 = w.z * scl, w11 = w.w * scl;
        __half2 h;
        uint4 ua;
        h = __float2half2_rn(w00); ua.x = *reinterpret_cast<unsigned*>(&h);
        h = __float2half2_rn(w01); ua.y = *reinterpret_cast<unsigned*>(&h);
        h = __float2half2_rn(w10); ua.z = *reinterpret_cast<unsigned*>(&h);
        h = __float2half2_rn(w11); ua.w = *reinterpret_cast<unsigned*>(&h);
        sA[tid] = ua;
        uint2 ub;
        h = __float2half2_rn(b.x); ub.x = *reinterpret_cast<unsigned*>(&h);
        h = __float2half2_rn(b.y); ub.y = *reinterpret_cast<unsigned*>(&h);
        sAb[tid] = ub;
        sB[tid][0] = make_ulonglong2(pk2(w00), pk2(w01));
        sB[tid][1] = make_ulonglong2(pk2(w10), pk2(w11));
        sB[tid][2] = make_ulonglong2(pk2(b.x), pk2(b.y));
    }
    if (tid < 4) sf[tid] = fW[tid];
    __syncthreads();

    const int wid  = tid >> 5;
    const int lane = tid & 31;
    const float f00 = sf[0], f01 = sf[1], f10 = sf[2], f11 = sf[3];
    const float4 zero4 = make_float4(0.f, 0.f, 0.f, 0.f);

    if (wid < 12) {
        // ====================== A class: MUFU half2 tanh =======================
        for (;;) {
            unsigned c = 0;
            if (lane == 0) c = atomicAdd(&g_ctrA, 1u);
            c = __shfl_sync(0xFFFFFFFFu, c, 0);
            if (c >= (unsigned)nchA) break;
            const int base = (int)c * ACHUNK;

            const int i0 = base + lane,      i1 = base + 32 + lane;
            const int i2 = base + 64 + lane, i3 = base + 96 + lane;
            const bool v0 = i0 < asplit, v1 = i1 < asplit,
                       v2 = i2 < asplit, v3 = i3 < asplit;
            float4 P0 = v0 ? pts[i0] : zero4;
            float4 P1 = v1 ? pts[i1] : zero4;
            float4 P2 = v2 ? pts[i2] : zero4;
            float4 P3 = v3 ? pts[i3] : zero4;

            __half2 Xa0 = __floats2half2_rn(P0.x, P0.z), Xa1 = __floats2half2_rn(P0.y, P0.w);
            __half2 Xb0 = __floats2half2_rn(P1.x, P1.z), Xb1 = __floats2half2_rn(P1.y, P1.w);
            __half2 Xc0 = __floats2half2_rn(P2.x, P2.z), Xc1 = __floats2half2_rn(P2.y, P2.w);
            __half2 Xd0 = __floats2half2_rn(P3.x, P3.z), Xd1 = __floats2half2_rn(P3.y, P3.w);

            #pragma unroll 2
            for (int l = 0; l < layers; ++l) {
                const uint4 ua = sA[l];
                const uint2 ub = sAb[l];
                const __half2 w00 = u2h(ua.x), w01 = u2h(ua.y);
                const __half2 w10 = u2h(ua.z), w11 = u2h(ua.w);
                const __half2 hb0 = u2h(ub.x), hb1 = u2h(ub.y);
                __half2 ya0 = __hfma2(w00, Xa0, __hfma2(w01, Xa1, hb0));
                __half2 ya1 = __hfma2(w10, Xa0, __hfma2(w11, Xa1, hb1));
                __half2 yb0 = __hfma2(w00, Xb0, __hfma2(w01, Xb1, hb0));
                __half2 yb1 = __hfma2(w10, Xb0, __hfma2(w11, Xb1, hb1));
                __half2 yc0 = __hfma2(w00, Xc0, __hfma2(w01, Xc1, hb0));
                __half2 yc1 = __hfma2(w10, Xc0, __hfma2(w11, Xc1, hb1));
                __half2 yd0 = __hfma2(w00, Xd0, __hfma2(w01, Xd1, hb0));
                __half2 yd1 = __hfma2(w10, Xd0, __hfma2(w11, Xd1, hb1));
                Xa0 = __hadd2(tanh_h2(ya0), ya0);
                Xa1 = __hadd2(tanh_h2(ya1), ya1);
                Xb0 = __hadd2(tanh_h2(yb0), yb0);
                Xb1 = __hadd2(tanh_h2(yb1), yb1);
                Xc0 = __hadd2(tanh_h2(yc0), yc0);
                Xc1 = __hadd2(tanh_h2(yc1), yc1);
                Xd0 = __hadd2(tanh_h2(yd0), yd0);
                Xd1 = __hadd2(tanh_h2(yd1), yd1);
            }

            {
                float2 a0 = __half22float2(Xa0), a1 = __half22float2(Xa1);
                float2 r0 = fin_norm(a0.x, a1.x, f00, f01, f10, f11);
                float2 r1 = fin_norm(a0.y, a1.y, f00, f01, f10, f11);
                if (v0) out[i0] = make_float4(r0.x, r0.y, r1.x, r1.y);
            }
            {
                float2 a0 = __half22float2(Xb0), a1 = __half22float2(Xb1);
                float2 r0 = fin_norm(a0.x, a1.x, f00, f01, f10, f11);
                float2 r1 = fin_norm(a0.y, a1.y, f00, f01, f10, f11);
                if (v1) out[i1] = make_float4(r0.x, r0.y, r1.x, r1.y);
            }
            {
                float2 a0 = __half22float2(Xc0), a1 = __half22float2(Xc1);
                float2 r0 = fin_norm(a0.x, a1.x, f00, f01, f10, f11);
                float2 r1 = fin_norm(a0.y, a1.y, f00, f01, f10, f11);
                if (v2) out[i2] = make_float4(r0.x, r0.y, r1.x, r1.y);
            }
            {
                float2 a0 = __half22float2(Xd0), a1 = __half22float2(Xd1);
                float2 r0 = fin_norm(a0.x, a1.x, f00, f01, f10, f11);
                float2 r1 = fin_norm(a0.y, a1.y, f00, f01, f10, f11);
                if (v3) out[i3] = make_float4(r0.x, r0.y, r1.x, r1.y);
            }
        }
    } else {
        // ====================== B class: fma-pipe tanh =========================
        for (;;) {
            unsigned c = 0;
            if (lane == 0) c = atomicAdd(&g_ctrB, 1u);
            c = __shfl_sync(0xFFFFFFFFu, c, 0);
            if (c >= (unsigned)nchB) break;
            const int base = asplit + (int)c * BCHUNK;

            const int i0 = base + lane, i1 = base + 32 + lane, i2 = base + 64 + lane;
            const bool v0 = i0 < nf4, v1 = i1 < nf4, v2 = i2 < nf4;
            float4 P0 = v0 ? pts[i0] : zero4;
            float4 P1 = v1 ? pts[i1] : zero4;
            float4 P2 = v2 ? pts[i2] : zero4;

            ull XP0 = pkf(P0.x, P0.z), XP1 = pkf(P0.y, P0.w);
            ull XQ0 = pkf(P1.x, P1.z), XQ1 = pkf(P1.y, P1.w);
            ull XR0 = pkf(P2.x, P2.z), XR1 = pkf(P2.y, P2.w);

            #pragma unroll 1
            for (int l = 0; l < layers; ++l) {
                const ulonglong2 q0 = sB[l][0];
                const ulonglong2 q1 = sB[l][1];
                const ulonglong2 q2 = sB[l][2];
                ull yp0 = f2fma(q0.x, XP0, f2fma(q0.y, XP1, q2.x));
                ull yp1 = f2fma(q1.x, XP0, f2fma(q1.y, XP1, q2.y));
                ull yq0 = f2fma(q0.x, XQ0, f2fma(q0.y, XQ1, q2.x));
                ull yq1 = f2fma(q1.x, XQ0, f2fma(q1.y, XQ1, q2.y));
                ull yr0 = f2fma(q0.x, XR0, f2fma(q0.y, XR1, q2.x));
                ull yr1 = f2fma(q1.x, XR0, f2fma(q1.y, XR1, q2.y));
                XP0 = f2add(tanh2_fma(yp0), yp0);
                XP1 = f2add(tanh2_fma(yp1), yp1);
                XQ0 = f2add(tanh2_fma(yq0), yq0);
                XQ1 = f2add(tanh2_fma(yq1), yq1);
                XR0 = f2add(tanh2_fma(yr0), yr0);
                XR1 = f2add(tanh2_fma(yr1), yr1);
            }

            {
                float x0a, x0b, x1a, x1b;
                unpkf(XP0, x0a, x0b);
                unpkf(XP1, x1a, x1b);
                float2 r0 = fin_norm(x0a, x1a, f00, f01, f10, f11);
                float2 r1 = fin_norm(x0b, x1b, f00, f01, f10, f11);
                if (v0) out[i0] = make_float4(r0.x, r0.y, r1.x, r1.y);
            }
            {
                float x0a, x0b, x1a, x1b;
                unpkf(XQ0, x0a, x0b);
                unpkf(XQ1, x1a, x1b);
                float2 r0 = fin_norm(x0a, x1a, f00, f01, f10, f11);
                float2 r1 = fin_norm(x0b, x1b, f00, f01, f10, f11);
                if (v1) out[i1] = make_float4(r0.x, r0.y, r1.x, r1.y);
            }
            {
                float x0a, x0b, x1a, x1b;
                unpkf(XR0, x0a, x0b);
                unpkf(XR1, x1a, x1b);
                float2 r0 = fin_norm(x0a, x1a, f00, f01, f10, f11);
                float2 r1 = fin_norm(x0b, x1b, f00, f01, f10, f11);
                if (v2) out[i2] = make_float4(r0.x, r0.y, r1.x, r1.y);
            }
        }
    }
}

extern "C" void kernel_launch(void* const* d_in, const int* in_sizes, int n_in,
                              void* d_out, int out_size) {
    // metadata order: T(1), closed_manifold(N*2), Ws(L*4), bs(L*2), final_W(4)
    const float* pts = (const float*)d_in[1];
    const float* Ws  = (const float*)d_in[2];
    const float* bs  = (const float*)d_in[3];
    const float* fW  = (const float*)d_in[4];
    float* out = (float*)d_out;

    const int n      = in_sizes[1] / 2;
    const int layers = in_sizes[2] / 4;
    const int nf4    = n / 2;

    // B class handles ~18% of the data (fma-pipe throughput share).
    long long a = ((long long)nf4 * 82) / 100;
    int asplit = (int)(a & ~127LL);          // ACHUNK-aligned
    if (asplit > nf4) asplit = nf4;
    const int nchA = (asplit + ACHUNK - 1) / ACHUNK;
    const int nchB = (nf4 - asplit + BCHUNK - 1) / BCHUNK;

    reset_ctr_kernel<<<1, 1>>>();
    nignet_kernel<<<NBLOCKS, TPB>>>(
        (const float4*)pts, Ws, bs, fW, (float4*)out,
        nf4, asplit, nchA, nchB, layers);
}